// round 7
// baseline (speedup 1.0000x reference)
#include <cuda_runtime.h>
#include <cstdint>

#define MDd 4
#define Bn 8
#define Cn 256
#define Hn 96
#define Wn 128
#define NDISP 81
#define NEG 0.1f

#define DEPTH 3
#define CH 2
#define NSTAGE (Cn / CH)          // 128
#define X1CHF (4 * 128)           // floats per (buf,k) x1 chunk: 4 rows x 128
#define X2ROWF 136                // x2 row: 4 halo + 128 + 4 halo
#define X2CHF (4 * X2ROWF)        // 544 floats per (buf,k) x2 chunk

typedef unsigned long long ull;

__device__ __forceinline__ void upk(ull v, float &lo, float &hi) {
    asm("mov.b64 {%0, %1}, %2;" : "=f"(lo), "=f"(hi) : "l"(v));
}
__device__ __forceinline__ ull pk(float lo, float hi) {
    ull r;
    asm("mov.b64 %0, {%1, %2};" : "=l"(r) : "f"(lo), "f"(hi));
    return r;
}
__device__ __forceinline__ ull fma2(ull a, ull b, ull c) {
    ull d;
    asm("fma.rn.f32x2 %0, %1, %2, %3;" : "=l"(d) : "l"(a), "l"(b), "l"(c));
    return d;
}
// (hi(a), lo(b))
__device__ __forceinline__ ull midpair(ull a, ull b) {
    ull r;
    asm("{\n\t"
        ".reg .b32 x,y,z,w;\n\t"
        "mov.b64 {x,y}, %1;\n\t"
        "mov.b64 {z,w}, %2;\n\t"
        "mov.b64 %0, {y,z};\n\t"
        "}" : "=l"(r) : "l"(a), "l"(b));
    return r;
}
__device__ __forceinline__ void cp16(uint32_t dst, const float* src) {
    asm volatile("cp.async.cg.shared.global [%0], [%1], 16;"
                 :: "r"(dst), "l"(src) : "memory");
}
__device__ __forceinline__ void cp_commit() {
    asm volatile("cp.async.commit_group;" ::: "memory");
}
__device__ __forceinline__ void cp_wait1() {
    asm volatile("cp.async.wait_group 1;" ::: "memory");
}

// Block: 128 threads = 4 warps, warp ty -> row h0+ty, lane tx -> w=4tx..4tx+3.
// blockIdx.y = dy. cp.async 3-stage x 2-channel smem pipeline; halo & OOB rows
// are zero-filled in smem once, so the compute body has no predication.
__global__ __launch_bounds__(128, 5)
void corr_kernel(const float* __restrict__ x1,
                 const float* __restrict__ x2,
                 float* __restrict__ out)
{
    __shared__ __align__(16) float s_x1[DEPTH * CH * X1CHF];   // 12 KB
    __shared__ __align__(16) float s_x2[DEPTH * CH * X2CHF];   // 13 KB

    const int tid = threadIdx.x;
    const int tx  = tid & 31;
    const int ty  = tid >> 5;
    const int h0  = blockIdx.x * 4;
    const int dy  = blockIdx.y;
    const int b   = blockIdx.z;
    const int h   = h0 + ty;

    // ---- producer role: row = warp id, seg = lane (16B each) ----
    const int prow = ty;
    const int pseg = tx;
    const int rrp  = h0 + prow + dy - MDd;
    const bool rvp = (rrp >= 0) && (rrp < Hn);
    const size_t CHW = (size_t)Hn * Wn;

    const float* x1cur = x1 + (size_t)b * Cn * CHW + (size_t)(h0 + prow) * Wn + 4 * pseg;
    const float* x2cur = x2 + (size_t)b * Cn * CHW + (size_t)(rvp ? rrp : 0) * Wn + 4 * pseg;

    const uint32_t s1b = (uint32_t)__cvta_generic_to_shared(s_x1);
    const uint32_t s2b = (uint32_t)__cvta_generic_to_shared(s_x2);
    const uint32_t d1 = s1b + (prow * 128 + 4 * pseg) * 4;          // within-chunk offset
    const uint32_t d2 = s2b + (prow * X2ROWF + 4 + 4 * pseg) * 4;   // +4: halo shift

    // ---- one-time zero of x2 halo cells and fully-OOB rows ----
    for (int i = tid; i < DEPTH * CH * X2CHF; i += 128) {
        int within = i % X2ROWF;
        int row    = (i / X2ROWF) & 3;
        int rr2    = h0 + row + dy - MDd;
        bool interior = (within >= 4) && (within < 132) && (rr2 >= 0) && (rr2 < Hn);
        if (!interior) s_x2[i] = 0.0f;
    }
    __syncthreads();

    // ---- pipeline prologue: issue stages 0,1 into bufs 0,1 ----
#pragma unroll
    for (int s = 0; s < DEPTH - 1; s++) {
#pragma unroll
        for (int k = 0; k < CH; k++) {
            uint32_t co = (uint32_t)(s * CH + k);
            cp16(d1 + co * (X1CHF * 4), x1cur + k * CHW);
            if (rvp) cp16(d2 + co * (X2CHF * 4), x2cur + k * CHW);
        }
        cp_commit();
        x1cur += CH * CHW;
        x2cur += CH * CHW;
    }

    ull acc[9][2];
#pragma unroll
    for (int dx = 0; dx < 9; dx++) { acc[dx][0] = 0ull; acc[dx][1] = 0ull; }

    int buf_c = 0;          // compute buffer
    int buf_i = DEPTH - 1;  // issue buffer

#pragma unroll 1
    for (int t = 0; t < NSTAGE; t++) {
        cp_wait1();
        __syncthreads();

        // issue stage t+2 into buf_i (empty commit past the end keeps counting uniform)
        if (t + (DEPTH - 1) < NSTAGE) {
#pragma unroll
            for (int k = 0; k < CH; k++) {
                uint32_t co = (uint32_t)(buf_i * CH + k);
                cp16(d1 + co * (X1CHF * 4), x1cur + k * CHW);
                if (rvp) cp16(d2 + co * (X2CHF * 4), x2cur + k * CHW);
            }
            x1cur += CH * CHW;
            x2cur += CH * CHW;
        }
        cp_commit();

        // compute CH channels from buf_c
#pragma unroll
        for (int k = 0; k < CH; k++) {
            const float* bx1 = &s_x1[(buf_c * CH + k) * X1CHF + ty * 128 + 4 * tx];
            const float* bx2 = &s_x2[(buf_c * CH + k) * X2CHF + ty * X2ROWF + 4 * tx];
            float4 a  = *(const float4*)bx1;
            float4 g0 = *(const float4*)(bx2);
            float4 g1 = *(const float4*)(bx2 + 4);
            float4 g2 = *(const float4*)(bx2 + 8);

            ull ax = pk(a.x, a.y);
            ull ay = pk(a.z, a.w);
            ull f2[6];
            f2[0] = pk(g0.x, g0.y); f2[1] = pk(g0.z, g0.w);
            f2[2] = pk(g1.x, g1.y); f2[3] = pk(g1.z, g1.w);
            f2[4] = pk(g2.x, g2.y); f2[5] = pk(g2.z, g2.w);
            ull o[5];
#pragma unroll
            for (int m = 0; m < 5; m++) o[m] = midpair(f2[m], f2[m + 1]);
#pragma unroll
            for (int dx = 0; dx < 9; dx++) {
                ull p0 = (dx & 1) ? o[dx >> 1] : f2[dx >> 1];
                int j1 = dx + 2;
                ull p1 = (j1 & 1) ? o[j1 >> 1] : f2[j1 >> 1];
                acc[dx][0] = fma2(ax, p0, acc[dx][0]);
                acc[dx][1] = fma2(ay, p1, acc[dx][1]);
            }
        }

        buf_c++; if (buf_c == DEPTH) buf_c = 0;
        buf_i++; if (buf_i == DEPTH) buf_i = 0;
    }

    // ---- epilogue: mean (1/256) + leaky relu, one STG.128 per dx ----
    const float scale = 1.0f / 256.0f;
#pragma unroll
    for (int dx = 0; dx < 9; dx++) {
        float v0, v1, v2, v3;
        upk(acc[dx][0], v0, v1);
        upk(acc[dx][1], v2, v3);
        v0 *= scale; v1 *= scale; v2 *= scale; v3 *= scale;
        float4 o4;
        o4.x = (v0 >= 0.0f) ? v0 : v0 * NEG;
        o4.y = (v1 >= 0.0f) ? v1 : v1 * NEG;
        o4.z = (v2 >= 0.0f) ? v2 : v2 * NEG;
        o4.w = (v3 >= 0.0f) ? v3 : v3 * NEG;
        int d = dy * 9 + dx;
        float* op = out + (((size_t)b * NDISP + d) * Hn + h) * Wn + 4 * tx;
        *(float4*)op = o4;
    }
}

extern "C" void kernel_launch(void* const* d_in, const int* in_sizes, int n_in,
                              void* d_out, int out_size)
{
    const float* x1 = (const float*)d_in[0];
    const float* x2 = (const float*)d_in[1];
    float* out = (float*)d_out;

    dim3 block(128);
    dim3 grid(Hn / 4, 9, Bn);   // 24 x 9 x 8 = 1728 blocks
    corr_kernel<<<grid, block>>>(x1, x2, out);
}